// round 5
// baseline (speedup 1.0000x reference)
#include <cuda_runtime.h>
#include <math.h>

typedef unsigned int u32;

#define Bz   2
#define Cz   128
#define Hz   64
#define Wz   128
#define HW   8192
#define NPIX 16384
#define NQ   6000
#define NQP  6016
#define NNEG 60
#define M0   14.2857151031494140625f   /* float(1/0.07) */
#define INVT 14.2857151031494140625f

// ---------------- scratch (device globals; no allocation) ----------------
__device__ __align__(16) float g_Q [NPIX * Cz];   // normalized query, [row][c]
__device__ __align__(16) float g_T [NPIX * Cz];   // tgt transposed,   [row][c]
__device__ __align__(16) float g_QN[Cz * NQP];    // normalized queue, [c][k] (padded cols zero)
__device__ float g_t [NPIX];   // per-row logits scale (mask ? 1/T : 0)
__device__ float g_dl[NPIX];   // per-row disparity
__device__ float g_Zs[NPIX];   // exp-sum of pos + 60 negs (shifted by M0)
__device__ float g_l0[NPIX];   // logit of class 0
__device__ float g_Zq[NPIX];   // exp-sum over queue logits (atomic)

// ---------------- threefry2x32 (JAX) ----------------
__device__ __forceinline__ void tfry(u32 k0, u32 k1, u32 x0, u32 x1, u32& o0, u32& o1) {
    u32 k2 = k0 ^ k1 ^ 0x1BD11BDAu;
    x0 += k0; x1 += k1;
#define RND4(a,b,c,d) \
    x0 += x1; x1 = __funnelshift_l(x1, x1, a); x1 ^= x0; \
    x0 += x1; x1 = __funnelshift_l(x1, x1, b); x1 ^= x0; \
    x0 += x1; x1 = __funnelshift_l(x1, x1, c); x1 ^= x0; \
    x0 += x1; x1 = __funnelshift_l(x1, x1, d); x1 ^= x0;
    RND4(13,15,26,6)   x0 += k1; x1 += k2 + 1u;
    RND4(17,29,16,24)  x0 += k2; x1 += k0 + 2u;
    RND4(13,15,26,6)   x0 += k0; x1 += k1 + 3u;
    RND4(17,29,16,24)  x0 += k1; x1 += k2 + 4u;
    RND4(13,15,26,6)   x0 += k2; x1 += k0 + 5u;
#undef RND4
    o0 = x0; o1 = x1;
}
__device__ __forceinline__ u32 rbits(u32 k0, u32 k1, u32 ctr) {
    u32 a, b; tfry(k0, k1, 0u, ctr, a, b); return a ^ b;
}

// ---------------- grid_sample axis helper (faithful to reference ops) ----------------
__device__ __forceinline__ void gs_axis(float g, int size, int& i0, int& i1, float& wf) {
    float gx = 2.0f * g - 1.0f;
    float ix = (gx + 1.0f) * ((float)size * 0.5f) - 0.5f;
    ix = fminf(fmaxf(ix, 0.0f), (float)(size - 1));
    float f0 = floorf(ix);
    i0 = (int)f0;
    i1 = min(i0 + 1, size - 1);
    wf = ix - f0;
}

// ---------------- stage A: disparities, occlusion mask ----------------
__global__ void k_mask(const float* __restrict__ tl, const float* __restrict__ tr) {
    int b = blockIdx.x;
    __shared__ float A[HW];                       // warp(index, disps_r)
    const float* TL = tl + b * (256 * 512);
    const float* TR = tr + b * (256 * 512);
    for (int p = threadIdx.x; p < HW; p += blockDim.x) {
        int h = p >> 7, w = p & 127;
        float dr = TR[(4 * h) * 512 + 4 * w] * 0.25f;
        float xb = (float)w * (1.0f / 127.0f);
        int x0, x1; float wx;
        gs_axis(xb + dr * (1.0f / 128.0f), Wz, x0, x1, wx);
        A[p] = (float)x0 * (1.0f - wx) + (float)x1 * wx;   // index img: value == column
    }
    __syncthreads();
    for (int p = threadIdx.x; p < HW; p += blockDim.x) {
        int h = p >> 7, w = p & 127;
        float dl = TL[(4 * h) * 512 + 4 * w] * 0.25f;
        float xb = (float)w * (1.0f / 127.0f);
        float yb = (float)h * (1.0f / 63.0f);
        int x0, x1, y0, y1; float wx, wy;
        gs_axis(xb - dl * (1.0f / 128.0f), Wz, x0, x1, wx);
        gs_axis(yb, Hz, y0, y1, wy);
        float v = A[y0 * Wz + x0] * (1.0f - wx) * (1.0f - wy)
                + A[y0 * Wz + x1] * wx * (1.0f - wy)
                + A[y1 * Wz + x0] * (1.0f - wx) * wy
                + A[y1 * Wz + x1] * wx * wy;
        bool m = (fabsf((float)w - v) < 3.0f) && (dl > 0.0f)
                 && (xb - dl * (1.0f / 128.0f) >= 0.0f);
        int row = b * HW + p;
        g_t [row] = m ? INVT : 0.0f;
        g_dl[row] = dl;
        g_Zq[row] = 0.0f;
    }
}

// ---------------- stage B: transpose [b,c,h,w] -> [row][c]; optional L2 normalize ----------------
__global__ void k_trans(const float* __restrict__ src, int do_norm) {
    int gw   = (blockIdx.x * blockDim.x + threadIdx.x) >> 5;   // one warp per pixel
    int lane = threadIdx.x & 31;
    if (gw >= NPIX) return;
    int b = gw >> 13, p = gw & (HW - 1);
    const float* S = src + b * Cz * HW + p;
    float v0 = S[(lane      ) * HW];
    float v1 = S[(lane + 32 ) * HW];
    float v2 = S[(lane + 64 ) * HW];
    float v3 = S[(lane + 96 ) * HW];
    float s = 1.0f;
    if (do_norm) {
        float ss = v0 * v0 + v1 * v1 + v2 * v2 + v3 * v3;
        #pragma unroll
        for (int o = 16; o; o >>= 1) ss += __shfl_xor_sync(0xffffffffu, ss, o);
        s = 1.0f / fmaxf(sqrtf(ss), 1e-12f);
    }
    float* D = (do_norm ? g_Q : g_T) + gw * Cz;
    D[lane] = v0 * s; D[lane + 32] = v1 * s; D[lane + 64] = v2 * s; D[lane + 96] = v3 * s;
}

// ---------------- stage C: normalize queue columns into [c][k] padded ----------------
__global__ void k_queue(const float* __restrict__ q) {
    int k = blockIdx.x * blockDim.x + threadIdx.x;
    if (k >= NQP) return;
    if (k >= NQ) {
        for (int c = 0; c < Cz; c++) g_QN[c * NQP + k] = 0.0f;
        return;
    }
    float ss = 0.0f;
    for (int c = 0; c < Cz; c++) { float v = q[c * NQ + k]; ss += v * v; }
    float inv = 1.0f / fmaxf(sqrtf(ss), 1e-12f);
    for (int c = 0; c < Cz; c++) g_QN[c * NQP + k] = q[c * NQ + k] * inv;
}

// ---------------- stage D: positive + 60 negatives per pixel ----------------
__global__ void k_posneg() {
    __shared__ __align__(16) float sq [8][Cz];
    __shared__ float sfx[8][NNEG];
    int wip = threadIdx.x >> 5, lane = threadIdx.x & 31;
    int row = blockIdx.x * 8 + wip;
    int b = row >> 13, p = row & (HW - 1);
    int h = p >> 7, w = p & 127;

    const float* Qr = g_Q + row * Cz;
    sq[wip][lane]      = Qr[lane];
    sq[wip][lane + 32] = Qr[lane + 32];
    sq[wip][lane + 64] = Qr[lane + 64];
    sq[wip][lane + 96] = Qr[lane + 96];

    float t  = g_t[row];
    float dl = g_dl[row];
    float xb = (float)w * (1.0f / 127.0f);
    float yb = (float)h * (1.0f / 63.0f);
    float gx = xb - dl * (1.0f / 128.0f);
    float xr = gx * 128.0f;                 // (xb - d/w) * w, reference order

    // RNG: lanes compute fx for the 60 negatives
    u32 ka0, ka1, kb0, kb1;
    tfry(0u, 1234u, 0u, 0u, ka0, ka1);      // split(key)[0] -> randint key
    tfry(0u, 1234u, 0u, 1u, kb0, kb1);      // split(key)[1] -> uniform key
    for (int n = lane; n < NNEG; n += 32) {
        u32 i  = (u32)(row * NNEG + n);
        u32 hi = rbits(ka0, ka1, i);
        u32 lo = rbits(ka0, ka1, (u32)(NPIX * NNEG) + i);
        float mag = 1.0f + (float)(((hi % 24u) * 16u + (lo % 24u)) % 24u);
        u32 ub = rbits(kb0, kb1, i);
        float u  = __uint_as_float((ub >> 9) | 0x3f800000u) - 1.0f;
        float sg = (u > 0.5f) ? 1.0f : ((u < 0.5f) ? -1.0f : 0.0f);
        float fv = xr + mag * sg;
        float m  = fmodf(fv, 128.0f); if (m < 0.0f) m += 128.0f;   // jnp.mod
        sfx[wip][n] = m * (1.0f / 128.0f);
    }
    __syncwarp();

    const float* T = g_T + b * HW * Cz;
    float4 q4 = ((const float4*)sq[wip])[lane];

    // positive
    int x0, x1, y0, y1; float wx, wy;
    gs_axis(gx, Wz, x0, x1, wx);
    gs_axis(yb, Hz, y0, y1, wy);
    float w00 = (1.0f - wx) * (1.0f - wy), w01 = wx * (1.0f - wy);
    float w10 = (1.0f - wx) * wy,          w11 = wx * wy;
    float4 A0 = ((const float4*)(T + (y0 * Wz + x0) * Cz))[lane];
    float4 A1 = ((const float4*)(T + (y0 * Wz + x1) * Cz))[lane];
    float4 A2 = ((const float4*)(T + (y1 * Wz + x0) * Cz))[lane];
    float4 A3 = ((const float4*)(T + (y1 * Wz + x1) * Cz))[lane];
    float vx = w00 * A0.x + w01 * A1.x + w10 * A2.x + w11 * A3.x;
    float vy = w00 * A0.y + w01 * A1.y + w10 * A2.y + w11 * A3.y;
    float vz = w00 * A0.z + w01 * A1.z + w10 * A2.z + w11 * A3.z;
    float vw = w00 * A0.w + w01 * A1.w + w10 * A2.w + w11 * A3.w;
    float qv = q4.x * vx + q4.y * vy + q4.z * vz + q4.w * vw;
    float vv = vx * vx + vy * vy + vz * vz + vw * vw;
    #pragma unroll
    for (int o = 16; o; o >>= 1) {
        qv += __shfl_xor_sync(0xffffffffu, qv, o);
        vv += __shfl_xor_sync(0xffffffffu, vv, o);
    }
    float lpos = qv / fmaxf(sqrtf(vv), 1e-12f);
    float l0   = lpos * t;
    float Zall = __expf(l0 - M0);

    // negatives (channel-parallel; taps live in rows 0/1 -> L1-resident slab)
    for (int n = 0; n < NNEG; n++) {
        float fx = sfx[wip][n];
        float fy = fx * (1.0f / 64.0f);
        int nx0, nx1, ny0, ny1; float nwx, nwy;
        gs_axis(fx, Wz, nx0, nx1, nwx);
        gs_axis(fy, Hz, ny0, ny1, nwy);
        float c00 = (1.0f - nwx) * (1.0f - nwy), c01 = nwx * (1.0f - nwy);
        float c10 = (1.0f - nwx) * nwy,          c11 = nwx * nwy;
        float4 B0 = ((const float4*)(T + (ny0 * Wz + nx0) * Cz))[lane];
        float4 B1 = ((const float4*)(T + (ny0 * Wz + nx1) * Cz))[lane];
        float4 B2 = ((const float4*)(T + (ny1 * Wz + nx0) * Cz))[lane];
        float4 B3 = ((const float4*)(T + (ny1 * Wz + nx1) * Cz))[lane];
        float ux = c00 * B0.x + c01 * B1.x + c10 * B2.x + c11 * B3.x;
        float uy = c00 * B0.y + c01 * B1.y + c10 * B2.y + c11 * B3.y;
        float uz = c00 * B0.z + c01 * B1.z + c10 * B2.z + c11 * B3.z;
        float uw = c00 * B0.w + c01 * B1.w + c10 * B2.w + c11 * B3.w;
        float nqv = q4.x * ux + q4.y * uy + q4.z * uz + q4.w * uw;
        float nvv = ux * ux + uy * uy + uz * uz + uw * uw;
        #pragma unroll
        for (int o = 16; o; o >>= 1) {
            nqv += __shfl_xor_sync(0xffffffffu, nqv, o);
            nvv += __shfl_xor_sync(0xffffffffu, nvv, o);
        }
        float ln = nqv / fmaxf(sqrtf(nvv), 1e-12f);
        Zall += __expf(ln * t - M0);
    }
    if (lane == 0) { g_Zs[row] = Zall; g_l0[row] = l0; }
}

// ---------------- stage E: fused GEMM (16384x6016x128) + exp row-sum ----------------
#define BM 128
#define BN 128
#define KC 8
__global__ __launch_bounds__(256, 2) void k_gemm() {
    __shared__ __align__(16) float As[KC][BM + 4];
    __shared__ __align__(16) float Bs[KC][BN];
    int tid = threadIdx.x;
    int tx = tid & 15, ty = tid >> 4;
    int row0 = blockIdx.y * BM;
    int col0 = blockIdx.x * BN;
    const float* Ag = g_Q  + row0 * Cz;
    const float* Bg = g_QN + col0;
    int aRow = tid >> 1, aCol = (tid & 1) * 4;
    int bRow = tid >> 5, bCol = (tid & 31) * 4;

    float acc[8][8] = {};
    float4 pa = *(const float4*)(Ag + aRow * Cz + aCol);
    float4 pb = *(const float4*)(Bg + bRow * NQP + bCol);

    for (int kc0 = 0; kc0 < Cz; kc0 += KC) {
        As[aCol + 0][aRow] = pa.x;
        As[aCol + 1][aRow] = pa.y;
        As[aCol + 2][aRow] = pa.z;
        As[aCol + 3][aRow] = pa.w;
        *(float4*)&Bs[bRow][bCol] = pb;
        __syncthreads();
        if (kc0 + KC < Cz) {
            pa = *(const float4*)(Ag + aRow * Cz + (kc0 + KC) + aCol);
            pb = *(const float4*)(Bg + (kc0 + KC + bRow) * NQP + bCol);
        }
        #pragma unroll
        for (int k = 0; k < KC; k++) {
            float4 a0 = *(const float4*)&As[k][ty * 8];
            float4 a1 = *(const float4*)&As[k][ty * 8 + 4];
            float4 b0 = *(const float4*)&Bs[k][tx * 8];
            float4 b1 = *(const float4*)&Bs[k][tx * 8 + 4];
            float a[8] = {a0.x, a0.y, a0.z, a0.w, a1.x, a1.y, a1.z, a1.w};
            float bb[8] = {b0.x, b0.y, b0.z, b0.w, b1.x, b1.y, b1.z, b1.w};
            #pragma unroll
            for (int i = 0; i < 8; i++)
                #pragma unroll
                for (int j = 0; j < 8; j++)
                    acc[i][j] += a[i] * bb[j];
        }
        __syncthreads();
    }

    // epilogue: exp + row partial sums (shift by M0; skip padded cols)
    #pragma unroll
    for (int i = 0; i < 8; i++) {
        int rg = row0 + ty * 8 + i;
        float trow = g_t[rg];
        float s = 0.0f;
        #pragma unroll
        for (int j = 0; j < 8; j++) {
            int cg = col0 + tx * 8 + j;
            if (cg < NQ) s += __expf(acc[i][j] * trow - M0);
        }
        #pragma unroll
        for (int o = 8; o; o >>= 1) s += __shfl_xor_sync(0xffffffffu, s, o);
        if (tx == 0) atomicAdd(&g_Zq[rg], s);
    }
}

// ---------------- stage F: final loss ----------------
__global__ void k_final(float* __restrict__ out) {
    __shared__ float red[1024];
    float s = 0.0f;
    for (int r = threadIdx.x; r < NPIX; r += 1024) {
        float Z = g_Zs[r] + g_Zq[r];
        s += M0 + logf(Z) - g_l0[r];
    }
    red[threadIdx.x] = s;
    __syncthreads();
    for (int o = 512; o; o >>= 1) {
        if (threadIdx.x < o) red[threadIdx.x] += red[threadIdx.x + o];
        __syncthreads();
    }
    if (threadIdx.x == 0) out[0] = red[0] * (1.0f / (float)NPIX);
}

// ---------------- launch ----------------
extern "C" void kernel_launch(void* const* d_in, const int* in_sizes, int n_in,
                              void* d_out, int out_size) {
    const float* ref = (const float*)d_in[0];
    const float* tgt = (const float*)d_in[1];
    const float* tl  = (const float*)d_in[2];
    const float* tr  = (const float*)d_in[3];
    const float* que = (const float*)d_in[4];

    k_mask  <<<Bz, 1024>>>(tl, tr);
    k_trans <<<2048, 256>>>(ref, 1);
    k_trans <<<2048, 256>>>(tgt, 0);
    k_queue <<<(NQP + 255) / 256, 256>>>(que);
    k_posneg<<<2048, 256>>>();
    dim3 gg(NQP / BN, NPIX / BM);
    k_gemm  <<<gg, 256>>>();
    k_final <<<1, 1024>>>((float*)d_out);
}

// round 7
// speedup vs baseline: 1.6343x; 1.6343x over previous
#include <cuda_runtime.h>
#include <math.h>

typedef unsigned int u32;

#define Bz   2
#define Cz   128
#define Hz   64
#define Wz   128
#define HW   8192
#define NPIX 16384
#define NQ   6000
#define NQP  6016
#define NNEG 60
#define M0   14.2857151031494140625f   /* float(1/0.07) */
#define INVT 14.2857151031494140625f

// ---------------- scratch (device globals; no allocation) ----------------
__device__ __align__(16) float g_Q [NPIX * Cz];   // normalized query fp32, [row][c]
__device__ __align__(16) float g_Qt[NPIX * Cz];   // tf32-rounded copy for the GEMM
__device__ __align__(16) float g_T [NPIX * Cz];   // tgt transposed,   [row][c]
__device__ __align__(16) float g_QN[Cz * NQP];    // normalized queue tf32, [c][k] (pad cols zero)
__device__ float g_t [NPIX];   // per-row logits scale (mask ? 1/T : 0)
__device__ float g_dl[NPIX];   // per-row disparity
__device__ float g_Zs[NPIX];   // exp-sum of pos + 60 negs (shifted by M0)
__device__ float g_l0[NPIX];   // logit of class 0
__device__ float g_Zq[NPIX];   // exp-sum over queue logits (atomic)

__device__ __forceinline__ float to_tf32(float x) {
    float r;
    asm("cvt.rna.tf32.f32 %0, %1;" : "=f"(r) : "f"(x));
    return r;
}

// ---------------- threefry2x32 (JAX) ----------------
__device__ __forceinline__ void tfry(u32 k0, u32 k1, u32 x0, u32 x1, u32& o0, u32& o1) {
    u32 k2 = k0 ^ k1 ^ 0x1BD11BDAu;
    x0 += k0; x1 += k1;
#define RND4(a,b,c,d) \
    x0 += x1; x1 = __funnelshift_l(x1, x1, a); x1 ^= x0; \
    x0 += x1; x1 = __funnelshift_l(x1, x1, b); x1 ^= x0; \
    x0 += x1; x1 = __funnelshift_l(x1, x1, c); x1 ^= x0; \
    x0 += x1; x1 = __funnelshift_l(x1, x1, d); x1 ^= x0;
    RND4(13,15,26,6)   x0 += k1; x1 += k2 + 1u;
    RND4(17,29,16,24)  x0 += k2; x1 += k0 + 2u;
    RND4(13,15,26,6)   x0 += k0; x1 += k1 + 3u;
    RND4(17,29,16,24)  x0 += k1; x1 += k2 + 4u;
    RND4(13,15,26,6)   x0 += k2; x1 += k0 + 5u;
#undef RND4
    o0 = x0; o1 = x1;
}
__device__ __forceinline__ u32 rbits(u32 k0, u32 k1, u32 ctr) {
    u32 a, b; tfry(k0, k1, 0u, ctr, a, b); return a ^ b;
}

// ---------------- grid_sample axis helper ----------------
__device__ __forceinline__ void gs_axis(float g, int size, int& i0, int& i1, float& wf) {
    float gx = 2.0f * g - 1.0f;
    float ix = (gx + 1.0f) * ((float)size * 0.5f) - 0.5f;
    ix = fminf(fmaxf(ix, 0.0f), (float)(size - 1));
    float f0 = floorf(ix);
    i0 = (int)f0;
    i1 = min(i0 + 1, size - 1);
    wf = ix - f0;
}

// ---------------- stage A: disparities, occlusion mask ----------------
__global__ void k_mask(const float* __restrict__ tl, const float* __restrict__ tr) {
    int b = blockIdx.x;
    __shared__ float A[HW];
    const float* TL = tl + b * (256 * 512);
    const float* TR = tr + b * (256 * 512);
    for (int p = threadIdx.x; p < HW; p += blockDim.x) {
        int h = p >> 7, w = p & 127;
        float dr = TR[(4 * h) * 512 + 4 * w] * 0.25f;
        float xb = (float)w * (1.0f / 127.0f);
        int x0, x1; float wx;
        gs_axis(xb + dr * (1.0f / 128.0f), Wz, x0, x1, wx);
        A[p] = (float)x0 * (1.0f - wx) + (float)x1 * wx;
    }
    __syncthreads();
    for (int p = threadIdx.x; p < HW; p += blockDim.x) {
        int h = p >> 7, w = p & 127;
        float dl = TL[(4 * h) * 512 + 4 * w] * 0.25f;
        float xb = (float)w * (1.0f / 127.0f);
        float yb = (float)h * (1.0f / 63.0f);
        int x0, x1, y0, y1; float wx, wy;
        gs_axis(xb - dl * (1.0f / 128.0f), Wz, x0, x1, wx);
        gs_axis(yb, Hz, y0, y1, wy);
        float v = A[y0 * Wz + x0] * (1.0f - wx) * (1.0f - wy)
                + A[y0 * Wz + x1] * wx * (1.0f - wy)
                + A[y1 * Wz + x0] * (1.0f - wx) * wy
                + A[y1 * Wz + x1] * wx * wy;
        bool m = (fabsf((float)w - v) < 3.0f) && (dl > 0.0f)
                 && (xb - dl * (1.0f / 128.0f) >= 0.0f);
        int row = b * HW + p;
        g_t [row] = m ? INVT : 0.0f;
        g_dl[row] = dl;
        g_Zq[row] = 0.0f;
    }
}

// ---------------- stage B: transpose; optional normalize (+ tf32 copy) ----------------
__global__ void k_trans(const float* __restrict__ src, int do_norm) {
    int gw   = (blockIdx.x * blockDim.x + threadIdx.x) >> 5;
    int lane = threadIdx.x & 31;
    if (gw >= NPIX) return;
    int b = gw >> 13, p = gw & (HW - 1);
    const float* S = src + b * Cz * HW + p;
    float v0 = S[(lane      ) * HW];
    float v1 = S[(lane + 32 ) * HW];
    float v2 = S[(lane + 64 ) * HW];
    float v3 = S[(lane + 96 ) * HW];
    float s = 1.0f;
    if (do_norm) {
        float ss = v0 * v0 + v1 * v1 + v2 * v2 + v3 * v3;
        #pragma unroll
        for (int o = 16; o; o >>= 1) ss += __shfl_xor_sync(0xffffffffu, ss, o);
        s = 1.0f / fmaxf(sqrtf(ss), 1e-12f);
    }
    v0 *= s; v1 *= s; v2 *= s; v3 *= s;
    float* D = (do_norm ? g_Q : g_T) + gw * Cz;
    D[lane] = v0; D[lane + 32] = v1; D[lane + 64] = v2; D[lane + 96] = v3;
    if (do_norm) {
        float* Dt = g_Qt + gw * Cz;
        Dt[lane]      = to_tf32(v0);
        Dt[lane + 32] = to_tf32(v1);
        Dt[lane + 64] = to_tf32(v2);
        Dt[lane + 96] = to_tf32(v3);
    }
}

// ---------------- stage C: normalize queue columns into [c][k] padded (tf32) ----------------
__global__ void k_queue(const float* __restrict__ q) {
    int k = blockIdx.x * blockDim.x + threadIdx.x;
    if (k >= NQP) return;
    if (k >= NQ) {
        for (int c = 0; c < Cz; c++) g_QN[c * NQP + k] = 0.0f;
        return;
    }
    float ss = 0.0f;
    for (int c = 0; c < Cz; c++) { float v = q[c * NQ + k]; ss += v * v; }
    float inv = 1.0f / fmaxf(sqrtf(ss), 1e-12f);
    for (int c = 0; c < Cz; c++) g_QN[c * NQP + k] = to_tf32(q[c * NQ + k] * inv);
}

// ---------------- stage D: positive + 60 negatives per pixel ----------------
__global__ void k_posneg() {
    __shared__ __align__(16) float sq [8][Cz];
    __shared__ float sfx[8][NNEG];
    int wip = threadIdx.x >> 5, lane = threadIdx.x & 31;
    int row = blockIdx.x * 8 + wip;
    int b = row >> 13, p = row & (HW - 1);
    int h = p >> 7, w = p & 127;

    const float* Qr = g_Q + row * Cz;
    sq[wip][lane]      = Qr[lane];
    sq[wip][lane + 32] = Qr[lane + 32];
    sq[wip][lane + 64] = Qr[lane + 64];
    sq[wip][lane + 96] = Qr[lane + 96];

    float t  = g_t[row];
    float dl = g_dl[row];
    float xb = (float)w * (1.0f / 127.0f);
    float yb = (float)h * (1.0f / 63.0f);
    float gx = xb - dl * (1.0f / 128.0f);
    float xr = gx * 128.0f;

    u32 ka0, ka1, kb0, kb1;
    tfry(0u, 1234u, 0u, 0u, ka0, ka1);
    tfry(0u, 1234u, 0u, 1u, kb0, kb1);
    for (int n = lane; n < NNEG; n += 32) {
        u32 i  = (u32)(row * NNEG + n);
        u32 hi = rbits(ka0, ka1, i);
        u32 lo = rbits(ka0, ka1, (u32)(NPIX * NNEG) + i);
        float mag = 1.0f + (float)(((hi % 24u) * 16u + (lo % 24u)) % 24u);
        u32 ub = rbits(kb0, kb1, i);
        float u  = __uint_as_float((ub >> 9) | 0x3f800000u) - 1.0f;
        float sg = (u > 0.5f) ? 1.0f : ((u < 0.5f) ? -1.0f : 0.0f);
        float fv = xr + mag * sg;
        float m  = fmodf(fv, 128.0f); if (m < 0.0f) m += 128.0f;
        sfx[wip][n] = m * (1.0f / 128.0f);
    }
    __syncwarp();

    const float* T = g_T + b * HW * Cz;
    float4 q4 = ((const float4*)sq[wip])[lane];

    int x0, x1, y0, y1; float wx, wy;
    gs_axis(gx, Wz, x0, x1, wx);
    gs_axis(yb, Hz, y0, y1, wy);
    float w00 = (1.0f - wx) * (1.0f - wy), w01 = wx * (1.0f - wy);
    float w10 = (1.0f - wx) * wy,          w11 = wx * wy;
    float4 A0 = ((const float4*)(T + (y0 * Wz + x0) * Cz))[lane];
    float4 A1 = ((const float4*)(T + (y0 * Wz + x1) * Cz))[lane];
    float4 A2 = ((const float4*)(T + (y1 * Wz + x0) * Cz))[lane];
    float4 A3 = ((const float4*)(T + (y1 * Wz + x1) * Cz))[lane];
    float vx = w00 * A0.x + w01 * A1.x + w10 * A2.x + w11 * A3.x;
    float vy = w00 * A0.y + w01 * A1.y + w10 * A2.y + w11 * A3.y;
    float vz = w00 * A0.z + w01 * A1.z + w10 * A2.z + w11 * A3.z;
    float vw = w00 * A0.w + w01 * A1.w + w10 * A2.w + w11 * A3.w;
    float qv = q4.x * vx + q4.y * vy + q4.z * vz + q4.w * vw;
    float vv = vx * vx + vy * vy + vz * vz + vw * vw;
    #pragma unroll
    for (int o = 16; o; o >>= 1) {
        qv += __shfl_xor_sync(0xffffffffu, qv, o);
        vv += __shfl_xor_sync(0xffffffffu, vv, o);
    }
    float lpos = qv / fmaxf(sqrtf(vv), 1e-12f);
    float l0   = lpos * t;
    float Zall = __expf(l0 - M0);

    for (int n = 0; n < NNEG; n++) {
        float fx = sfx[wip][n];
        float fy = fx * (1.0f / 64.0f);
        int nx0, nx1, ny0, ny1; float nwx, nwy;
        gs_axis(fx, Wz, nx0, nx1, nwx);
        gs_axis(fy, Hz, ny0, ny1, nwy);
        float c00 = (1.0f - nwx) * (1.0f - nwy), c01 = nwx * (1.0f - nwy);
        float c10 = (1.0f - nwx) * nwy,          c11 = nwx * nwy;
        float4 B0 = ((const float4*)(T + (ny0 * Wz + nx0) * Cz))[lane];
        float4 B1 = ((const float4*)(T + (ny0 * Wz + nx1) * Cz))[lane];
        float4 B2 = ((const float4*)(T + (ny1 * Wz + nx0) * Cz))[lane];
        float4 B3 = ((const float4*)(T + (ny1 * Wz + nx1) * Cz))[lane];
        float ux = c00 * B0.x + c01 * B1.x + c10 * B2.x + c11 * B3.x;
        float uy = c00 * B0.y + c01 * B1.y + c10 * B2.y + c11 * B3.y;
        float uz = c00 * B0.z + c01 * B1.z + c10 * B2.z + c11 * B3.z;
        float uw = c00 * B0.w + c01 * B1.w + c10 * B2.w + c11 * B3.w;
        float nqv = q4.x * ux + q4.y * uy + q4.z * uz + q4.w * uw;
        float nvv = ux * ux + uy * uy + uz * uz + uw * uw;
        #pragma unroll
        for (int o = 16; o; o >>= 1) {
            nqv += __shfl_xor_sync(0xffffffffu, nqv, o);
            nvv += __shfl_xor_sync(0xffffffffu, nvv, o);
        }
        float ln = nqv / fmaxf(sqrtf(nvv), 1e-12f);
        Zall += __expf(ln * t - M0);
    }
    if (lane == 0) { g_Zs[row] = Zall; g_l0[row] = l0; }
}

// ---------------- stage E: tensor-core GEMM (tf32 mma) + exp row-sum ----------------
// D[16384 x 6016] = Qt[16384 x 128] * QN[128 x 6016]; block tile 128x128,
// 8 warps of 64(m) x 32(n), mma.m16n8k8.tf32.
#define LDA 36   /* padded smem stride: bank = (4*row + k) % 32 -> conflict-free frags */
__global__ __launch_bounds__(256, 2) void k_gemm_mma() {
    __shared__ __align__(16) float As[128 * LDA];   // [m][k]
    __shared__ __align__(16) float Bs[128 * LDA];   // [n][k]
    int tid  = threadIdx.x;
    int lane = tid & 31, wid = tid >> 5;
    int gid  = lane >> 2, t4 = lane & 3;
    int warpM = (wid & 1) * 64;
    int warpN = (wid >> 1) * 32;
    int row0 = blockIdx.y * 128;
    int col0 = blockIdx.x * 128;

    const float* Ag = g_Qt + row0 * Cz;
    const float* Bg = g_QN + col0;

    float acc[4][4][4];
    #pragma unroll
    for (int a = 0; a < 4; a++)
        #pragma unroll
        for (int b = 0; b < 4; b++)
            #pragma unroll
            for (int c = 0; c < 4; c++) acc[a][b][c] = 0.0f;

    int lmA = tid >> 3;           // 0..31 (A loader row within 32-row group)
    int lkA = (tid & 7) * 4;      // 0..28 (A loader k, float4)
    int lnB = tid >> 3;           // B loader n/4 index 0..31
    int lkB = tid & 7;            // B loader k within 8-row group

    for (int kc = 0; kc < Cz; kc += 32) {
        // A: 128m x 32k, float4 along k, sts.128 (conflict-free per 8-lane phase)
        #pragma unroll
        for (int mb = 0; mb < 4; mb++) {
            int m = mb * 32 + lmA;
            float4 v = *(const float4*)(Ag + m * Cz + kc + lkA);
            *(float4*)&As[m * LDA + lkA] = v;
        }
        // B: 32k x 128n in gmem, transposed into Bs[n][k]
        #pragma unroll
        for (int kb = 0; kb < 4; kb++) {
            int k = kc + kb * 8 + lkB;
            int n = lnB * 4;
            float4 v = *(const float4*)(Bg + k * NQP + n);
            int kk = kb * 8 + lkB;
            Bs[(n + 0) * LDA + kk] = v.x;
            Bs[(n + 1) * LDA + kk] = v.y;
            Bs[(n + 2) * LDA + kk] = v.z;
            Bs[(n + 3) * LDA + kk] = v.w;
        }
        __syncthreads();
        #pragma unroll
        for (int kk = 0; kk < 32; kk += 8) {
            u32 afr[4][4]; u32 bfr[4][2];
            #pragma unroll
            for (int mt = 0; mt < 4; mt++) {
                int mr = warpM + mt * 16 + gid;
                afr[mt][0] = __float_as_uint(As[ mr      * LDA + kk + t4    ]);
                afr[mt][1] = __float_as_uint(As[(mr + 8) * LDA + kk + t4    ]);
                afr[mt][2] = __float_as_uint(As[ mr      * LDA + kk + t4 + 4]);
                afr[mt][3] = __float_as_uint(As[(mr + 8) * LDA + kk + t4 + 4]);
            }
            #pragma unroll
            for (int nt = 0; nt < 4; nt++) {
                int nr = warpN + nt * 8 + gid;
                bfr[nt][0] = __float_as_uint(Bs[nr * LDA + kk + t4    ]);
                bfr[nt][1] = __float_as_uint(Bs[nr * LDA + kk + t4 + 4]);
            }
            #pragma unroll
            for (int mt = 0; mt < 4; mt++)
                #pragma unroll
                for (int nt = 0; nt < 4; nt++) {
                    float* d = acc[mt][nt];
                    asm volatile(
                        "mma.sync.aligned.m16n8k8.row.col.f32.tf32.tf32.f32 "
                        "{%0,%1,%2,%3}, {%4,%5,%6,%7}, {%8,%9}, {%0,%1,%2,%3};"
                        : "+f"(d[0]), "+f"(d[1]), "+f"(d[2]), "+f"(d[3])
                        : "r"(afr[mt][0]), "r"(afr[mt][1]), "r"(afr[mt][2]), "r"(afr[mt][3]),
                          "r"(bfr[nt][0]), "r"(bfr[nt][1]));
                }
        }
        __syncthreads();
    }

    // epilogue: exp + row partial sums (skip padded cols >= NQ)
    #pragma unroll
    for (int mt = 0; mt < 4; mt++) {
        #pragma unroll
        for (int half = 0; half < 2; half++) {
            int rg = row0 + warpM + mt * 16 + gid + half * 8;
            float trow = g_t[rg];
            float s = 0.0f;
            #pragma unroll
            for (int nt = 0; nt < 4; nt++) {
                #pragma unroll
                for (int i = 0; i < 2; i++) {
                    int cg = col0 + warpN + nt * 8 + 2 * t4 + i;
                    float v = acc[mt][nt][half * 2 + i];
                    if (cg < NQ) s += __expf(v * trow - M0);
                }
            }
            s += __shfl_xor_sync(0xffffffffu, s, 1);
            s += __shfl_xor_sync(0xffffffffu, s, 2);
            if (t4 == 0) atomicAdd(&g_Zq[rg], s);
        }
    }
}

// ---------------- stage F: final loss ----------------
__global__ void k_final(float* __restrict__ out) {
    __shared__ float red[1024];
    float s = 0.0f;
    for (int r = threadIdx.x; r < NPIX; r += 1024) {
        float Z = g_Zs[r] + g_Zq[r];
        s += M0 + logf(Z) - g_l0[r];
    }
    red[threadIdx.x] = s;
    __syncthreads();
    for (int o = 512; o; o >>= 1) {
        if (threadIdx.x < o) red[threadIdx.x] += red[threadIdx.x + o];
        __syncthreads();
    }
    if (threadIdx.x == 0) out[0] = red[0] * (1.0f / (float)NPIX);
}

// ---------------- launch ----------------
extern "C" void kernel_launch(void* const* d_in, const int* in_sizes, int n_in,
                              void* d_out, int out_size) {
    const float* ref = (const float*)d_in[0];
    const float* tgt = (const float*)d_in[1];
    const float* tl  = (const float*)d_in[2];
    const float* tr  = (const float*)d_in[3];
    const float* que = (const float*)d_in[4];

    k_mask  <<<Bz, 1024>>>(tl, tr);
    k_trans <<<2048, 256>>>(ref, 1);
    k_trans <<<2048, 256>>>(tgt, 0);
    k_queue <<<(NQP + 255) / 256, 256>>>(que);
    k_posneg<<<2048, 256>>>();
    dim3 gg(NQP / 128, NPIX / 128);
    k_gemm_mma<<<gg, 256>>>();
    k_final <<<1, 1024>>>((float*)d_out);
}

// round 9
// speedup vs baseline: 2.2269x; 1.3626x over previous
#include <cuda_runtime.h>
#include <cuda_bf16.h>
#include <math.h>

typedef unsigned int u32;

#define Bz   2
#define Cz   128
#define Hz   64
#define Wz   128
#define HW   8192
#define NPIX 16384
#define NQ   6000
#define NQP  6016
#define NNEG 60
#define M0   14.2857151031494140625f   /* float(1/0.07) */
#define INVT 14.2857151031494140625f

// ---------------- scratch (device globals; no allocation) ----------------
__device__ __align__(16) float g_Q [NPIX * Cz];            // normalized query fp32, [row][c]
__device__ __align__(16) float g_T [NPIX * Cz];            // tgt transposed,   [row][c]
__device__ __align__(16) __nv_bfloat16 g_Qb [NPIX * Cz];   // bf16 query for GEMM, [row][c]
__device__ __align__(16) __nv_bfloat16 g_QNb[Cz * NQP];    // bf16 queue, [c][k] (pad cols zero)
__device__ float g_t [NPIX];   // per-row logits scale (mask ? 1/T : 0)
__device__ float g_dl[NPIX];   // per-row disparity
__device__ float g_Zs[NPIX];   // exp-sum of pos + 60 negs (shifted by M0)
__device__ float g_l0[NPIX];   // logit of class 0
__device__ float g_Zq[NPIX];   // exp-sum over queue logits (atomic)

// ---------------- threefry2x32 (JAX) ----------------
__device__ __forceinline__ void tfry(u32 k0, u32 k1, u32 x0, u32 x1, u32& o0, u32& o1) {
    u32 k2 = k0 ^ k1 ^ 0x1BD11BDAu;
    x0 += k0; x1 += k1;
#define RND4(a,b,c,d) \
    x0 += x1; x1 = __funnelshift_l(x1, x1, a); x1 ^= x0; \
    x0 += x1; x1 = __funnelshift_l(x1, x1, b); x1 ^= x0; \
    x0 += x1; x1 = __funnelshift_l(x1, x1, c); x1 ^= x0; \
    x0 += x1; x1 = __funnelshift_l(x1, x1, d); x1 ^= x0;
    RND4(13,15,26,6)   x0 += k1; x1 += k2 + 1u;
    RND4(17,29,16,24)  x0 += k2; x1 += k0 + 2u;
    RND4(13,15,26,6)   x0 += k0; x1 += k1 + 3u;
    RND4(17,29,16,24)  x0 += k1; x1 += k2 + 4u;
    RND4(13,15,26,6)   x0 += k2; x1 += k0 + 5u;
#undef RND4
    o0 = x0; o1 = x1;
}
__device__ __forceinline__ u32 rbits(u32 k0, u32 k1, u32 ctr) {
    u32 a, b; tfry(k0, k1, 0u, ctr, a, b); return a ^ b;
}

// ---------------- grid_sample axis helper ----------------
__device__ __forceinline__ void gs_axis(float g, int size, int& i0, int& i1, float& wf) {
    float gx = 2.0f * g - 1.0f;
    float ix = (gx + 1.0f) * ((float)size * 0.5f) - 0.5f;
    ix = fminf(fmaxf(ix, 0.0f), (float)(size - 1));
    float f0 = floorf(ix);
    i0 = (int)f0;
    i1 = min(i0 + 1, size - 1);
    wf = ix - f0;
}

// ---------------- stage A: disparities, occlusion mask ----------------
__global__ void k_mask(const float* __restrict__ tl, const float* __restrict__ tr) {
    int b = blockIdx.x;
    __shared__ float A[HW];
    const float* TL = tl + b * (256 * 512);
    const float* TR = tr + b * (256 * 512);
    for (int p = threadIdx.x; p < HW; p += blockDim.x) {
        int h = p >> 7, w = p & 127;
        float dr = TR[(4 * h) * 512 + 4 * w] * 0.25f;
        float xb = (float)w * (1.0f / 127.0f);
        int x0, x1; float wx;
        gs_axis(xb + dr * (1.0f / 128.0f), Wz, x0, x1, wx);
        A[p] = (float)x0 * (1.0f - wx) + (float)x1 * wx;
    }
    __syncthreads();
    for (int p = threadIdx.x; p < HW; p += blockDim.x) {
        int h = p >> 7, w = p & 127;
        float dl = TL[(4 * h) * 512 + 4 * w] * 0.25f;
        float xb = (float)w * (1.0f / 127.0f);
        float yb = (float)h * (1.0f / 63.0f);
        int x0, x1, y0, y1; float wx, wy;
        gs_axis(xb - dl * (1.0f / 128.0f), Wz, x0, x1, wx);
        gs_axis(yb, Hz, y0, y1, wy);
        float v = A[y0 * Wz + x0] * (1.0f - wx) * (1.0f - wy)
                + A[y0 * Wz + x1] * wx * (1.0f - wy)
                + A[y1 * Wz + x0] * (1.0f - wx) * wy
                + A[y1 * Wz + x1] * wx * wy;
        bool m = (fabsf((float)w - v) < 3.0f) && (dl > 0.0f)
                 && (xb - dl * (1.0f / 128.0f) >= 0.0f);
        int row = b * HW + p;
        g_t [row] = m ? INVT : 0.0f;
        g_dl[row] = dl;
        g_Zq[row] = 0.0f;
    }
}

// ---------------- stage B: transpose; optional normalize (+ bf16 copy) ----------------
__global__ void k_trans(const float* __restrict__ src, int do_norm) {
    int gw   = (blockIdx.x * blockDim.x + threadIdx.x) >> 5;
    int lane = threadIdx.x & 31;
    if (gw >= NPIX) return;
    int b = gw >> 13, p = gw & (HW - 1);
    const float* S = src + b * Cz * HW + p;
    float v0 = S[(lane      ) * HW];
    float v1 = S[(lane + 32 ) * HW];
    float v2 = S[(lane + 64 ) * HW];
    float v3 = S[(lane + 96 ) * HW];
    float s = 1.0f;
    if (do_norm) {
        float ss = v0 * v0 + v1 * v1 + v2 * v2 + v3 * v3;
        #pragma unroll
        for (int o = 16; o; o >>= 1) ss += __shfl_xor_sync(0xffffffffu, ss, o);
        s = 1.0f / fmaxf(sqrtf(ss), 1e-12f);
    }
    v0 *= s; v1 *= s; v2 *= s; v3 *= s;
    float* D = (do_norm ? g_Q : g_T) + gw * Cz;
    D[lane] = v0; D[lane + 32] = v1; D[lane + 64] = v2; D[lane + 96] = v3;
    if (do_norm) {
        __nv_bfloat16* Db = g_Qb + gw * Cz;
        Db[lane]      = __float2bfloat16_rn(v0);
        Db[lane + 32] = __float2bfloat16_rn(v1);
        Db[lane + 64] = __float2bfloat16_rn(v2);
        Db[lane + 96] = __float2bfloat16_rn(v3);
    }
}

// ---------------- stage C: normalize queue columns into [c][k] padded (bf16) ----------------
__global__ void k_queue(const float* __restrict__ q) {
    int k = blockIdx.x * blockDim.x + threadIdx.x;
    if (k >= NQP) return;
    if (k >= NQ) {
        for (int c = 0; c < Cz; c++) g_QNb[c * NQP + k] = __float2bfloat16_rn(0.0f);
        return;
    }
    float ss = 0.0f;
    for (int c = 0; c < Cz; c++) { float v = q[c * NQ + k]; ss += v * v; }
    float inv = 1.0f / fmaxf(sqrtf(ss), 1e-12f);
    for (int c = 0; c < Cz; c++)
        g_QNb[c * NQP + k] = __float2bfloat16_rn(q[c * NQ + k] * inv);
}

// ---------------- stage D: positive + 60 negatives per pixel ----------------
__global__ void k_posneg() {
    __shared__ __align__(16) float sq [8][Cz];
    __shared__ float sfx[8][NNEG];
    int wip = threadIdx.x >> 5, lane = threadIdx.x & 31;
    int row = blockIdx.x * 8 + wip;
    int b = row >> 13, p = row & (HW - 1);
    int h = p >> 7, w = p & 127;

    const float* Qr = g_Q + row * Cz;
    sq[wip][lane]      = Qr[lane];
    sq[wip][lane + 32] = Qr[lane + 32];
    sq[wip][lane + 64] = Qr[lane + 64];
    sq[wip][lane + 96] = Qr[lane + 96];

    float t  = g_t[row];
    float dl = g_dl[row];
    float xb = (float)w * (1.0f / 127.0f);
    float yb = (float)h * (1.0f / 63.0f);
    float gx = xb - dl * (1.0f / 128.0f);
    float xr = gx * 128.0f;

    u32 ka0, ka1, kb0, kb1;
    tfry(0u, 1234u, 0u, 0u, ka0, ka1);
    tfry(0u, 1234u, 0u, 1u, kb0, kb1);
    for (int n = lane; n < NNEG; n += 32) {
        u32 i  = (u32)(row * NNEG + n);
        u32 hi = rbits(ka0, ka1, i);
        u32 lo = rbits(ka0, ka1, (u32)(NPIX * NNEG) + i);
        float mag = 1.0f + (float)(((hi % 24u) * 16u + (lo % 24u)) % 24u);
        u32 ub = rbits(kb0, kb1, i);
        float u  = __uint_as_float((ub >> 9) | 0x3f800000u) - 1.0f;
        float sg = (u > 0.5f) ? 1.0f : ((u < 0.5f) ? -1.0f : 0.0f);
        float fv = xr + mag * sg;
        float m  = fmodf(fv, 128.0f); if (m < 0.0f) m += 128.0f;
        sfx[wip][n] = m * (1.0f / 128.0f);
    }
    __syncwarp();

    const float* T = g_T + b * HW * Cz;
    float4 q4 = ((const float4*)sq[wip])[lane];

    int x0, x1, y0, y1; float wx, wy;
    gs_axis(gx, Wz, x0, x1, wx);
    gs_axis(yb, Hz, y0, y1, wy);
    float w00 = (1.0f - wx) * (1.0f - wy), w01 = wx * (1.0f - wy);
    float w10 = (1.0f - wx) * wy,          w11 = wx * wy;
    float4 A0 = ((const float4*)(T + (y0 * Wz + x0) * Cz))[lane];
    float4 A1 = ((const float4*)(T + (y0 * Wz + x1) * Cz))[lane];
    float4 A2 = ((const float4*)(T + (y1 * Wz + x0) * Cz))[lane];
    float4 A3 = ((const float4*)(T + (y1 * Wz + x1) * Cz))[lane];
    float vx = w00 * A0.x + w01 * A1.x + w10 * A2.x + w11 * A3.x;
    float vy = w00 * A0.y + w01 * A1.y + w10 * A2.y + w11 * A3.y;
    float vz = w00 * A0.z + w01 * A1.z + w10 * A2.z + w11 * A3.z;
    float vw = w00 * A0.w + w01 * A1.w + w10 * A2.w + w11 * A3.w;
    float qv = q4.x * vx + q4.y * vy + q4.z * vz + q4.w * vw;
    float vv = vx * vx + vy * vy + vz * vz + vw * vw;
    #pragma unroll
    for (int o = 16; o; o >>= 1) {
        qv += __shfl_xor_sync(0xffffffffu, qv, o);
        vv += __shfl_xor_sync(0xffffffffu, vv, o);
    }
    float lpos = qv / fmaxf(sqrtf(vv), 1e-12f);
    float l0   = lpos * t;
    float Zall = __expf(l0 - M0);

    for (int n = 0; n < NNEG; n++) {
        float fx = sfx[wip][n];
        float fy = fx * (1.0f / 64.0f);
        int nx0, nx1, ny0, ny1; float nwx, nwy;
        gs_axis(fx, Wz, nx0, nx1, nwx);
        gs_axis(fy, Hz, ny0, ny1, nwy);
        float c00 = (1.0f - nwx) * (1.0f - nwy), c01 = nwx * (1.0f - nwy);
        float c10 = (1.0f - nwx) * nwy,          c11 = nwx * nwy;
        float4 B0 = ((const float4*)(T + (ny0 * Wz + nx0) * Cz))[lane];
        float4 B1 = ((const float4*)(T + (ny0 * Wz + nx1) * Cz))[lane];
        float4 B2 = ((const float4*)(T + (ny1 * Wz + nx0) * Cz))[lane];
        float4 B3 = ((const float4*)(T + (ny1 * Wz + nx1) * Cz))[lane];
        float ux = c00 * B0.x + c01 * B1.x + c10 * B2.x + c11 * B3.x;
        float uy = c00 * B0.y + c01 * B1.y + c10 * B2.y + c11 * B3.y;
        float uz = c00 * B0.z + c01 * B1.z + c10 * B2.z + c11 * B3.z;
        float uw = c00 * B0.w + c01 * B1.w + c10 * B2.w + c11 * B3.w;
        float nqv = q4.x * ux + q4.y * uy + q4.z * uz + q4.w * uw;
        float nvv = ux * ux + uy * uy + uz * uz + uw * uw;
        #pragma unroll
        for (int o = 16; o; o >>= 1) {
            nqv += __shfl_xor_sync(0xffffffffu, nqv, o);
            nvv += __shfl_xor_sync(0xffffffffu, nvv, o);
        }
        float ln = nqv / fmaxf(sqrtf(nvv), 1e-12f);
        Zall += __expf(ln * t - M0);
    }
    if (lane == 0) { g_Zs[row] = Zall; g_l0[row] = l0; }
}

// ---------------- stage E: bf16 tensor-core GEMM + exp row-sum ----------------
// D[16384 x 6016] = Qb[16384 x 128] * QNb[128 x 6016]; 128x128 block tile,
// 8 warps of 64(m) x 32(n), mma.m16n8k16.bf16, ldmatrix fragments.
#define LDAe 72    /* A smem stride (bf16): 64 k + 8 pad -> 144B = 4 banks mod 32 */
#define LDBe 136   /* B smem stride (bf16): 128 n + 8 pad -> 272B = 4 banks mod 32 */
__global__ __launch_bounds__(256, 2) void k_gemm_bf16() {
    __shared__ __align__(16) __nv_bfloat16 As[128 * LDAe];  // [m][k], K chunk = 64
    __shared__ __align__(16) __nv_bfloat16 Bs[64 * LDBe];   // [k][n]
    int tid  = threadIdx.x;
    int lane = tid & 31, wid = tid >> 5;
    int gid  = lane >> 2, t4 = lane & 3;
    int warpM = (wid & 1) * 64;
    int warpN = (wid >> 1) * 32;
    int row0 = blockIdx.y * 128;
    int col0 = blockIdx.x * 128;

    const __nv_bfloat16* Ag = g_Qb  + row0 * Cz;
    const __nv_bfloat16* Bg = g_QNb + col0;

    u32 asB = (u32)__cvta_generic_to_shared(As);
    u32 bsB = (u32)__cvta_generic_to_shared(Bs);

    // ldmatrix per-lane address components
    int aR = (lane & 7) + ((lane >> 3) & 1) * 8;   // row within 16 (blk0/1 rows, blk2/3 rows)
    int aK = (lane >> 4) * 8;                      // k half (0 or 8)
    int bK = (lane & 7) + ((lane >> 3) & 1) * 8;   // k within 16
    int bN = (lane >> 4) * 8;                      // n half (0 or 8)

    float acc[4][4][4];
    #pragma unroll
    for (int a = 0; a < 4; a++)
        #pragma unroll
        for (int b = 0; b < 4; b++)
            #pragma unroll
            for (int c = 0; c < 4; c++) acc[a][b][c] = 0.0f;

    #pragma unroll
    for (int kc = 0; kc < Cz; kc += 64) {
        // A: 128m x 64k, 16B per thread per pass (8 bf16 along k)
        #pragma unroll
        for (int pass = 0; pass < 4; pass++) {
            int m  = pass * 32 + (tid >> 3);
            int k8 = (tid & 7) * 8;
            uint4 v = *(const uint4*)(Ag + m * Cz + kc + k8);
            *(uint4*)&As[m * LDAe + k8] = v;
        }
        // B: 64k x 128n, 16B per thread per pass (8 bf16 along n)
        #pragma unroll
        for (int pass = 0; pass < 4; pass++) {
            int k = pass * 16 + (tid >> 4);
            int n = (tid & 15) * 8;
            uint4 v = *(const uint4*)(Bg + (kc + k) * NQP + n);
            *(uint4*)&Bs[k * LDBe + n] = v;
        }
        __syncthreads();

        #pragma unroll
        for (int kk = 0; kk < 64; kk += 16) {
            u32 afr[4][4]; u32 bfr[4][2];
            #pragma unroll
            for (int mt = 0; mt < 4; mt++) {
                u32 addr = asB + ((warpM + mt * 16 + aR) * LDAe + kk + aK) * 2;
                asm volatile("ldmatrix.sync.aligned.m8n8.x4.shared.b16 {%0,%1,%2,%3}, [%4];"
                             : "=r"(afr[mt][0]), "=r"(afr[mt][1]),
                               "=r"(afr[mt][2]), "=r"(afr[mt][3]) : "r"(addr));
            }
            #pragma unroll
            for (int np = 0; np < 2; np++) {
                u32 addr = bsB + ((kk + bK) * LDBe + warpN + np * 16 + bN) * 2;
                asm volatile("ldmatrix.sync.aligned.m8n8.x4.trans.shared.b16 {%0,%1,%2,%3}, [%4];"
                             : "=r"(bfr[np * 2][0]),     "=r"(bfr[np * 2][1]),
                               "=r"(bfr[np * 2 + 1][0]), "=r"(bfr[np * 2 + 1][1]) : "r"(addr));
            }
            #pragma unroll
            for (int mt = 0; mt < 4; mt++)
                #pragma unroll
                for (int nt = 0; nt < 4; nt++) {
                    float* d = acc[mt][nt];
                    asm volatile(
                        "mma.sync.aligned.m16n8k16.row.col.f32.bf16.bf16.f32 "
                        "{%0,%1,%2,%3}, {%4,%5,%6,%7}, {%8,%9}, {%0,%1,%2,%3};"
                        : "+f"(d[0]), "+f"(d[1]), "+f"(d[2]), "+f"(d[3])
                        : "r"(afr[mt][0]), "r"(afr[mt][1]), "r"(afr[mt][2]), "r"(afr[mt][3]),
                          "r"(bfr[nt][0]), "r"(bfr[nt][1]));
                }
        }
        __syncthreads();
    }

    // epilogue: exp + row partial sums (skip padded cols >= NQ)
    #pragma unroll
    for (int mt = 0; mt < 4; mt++) {
        #pragma unroll
        for (int half = 0; half < 2; half++) {
            int rg = row0 + warpM + mt * 16 + gid + half * 8;
            float trow = g_t[rg];
            float s = 0.0f;
            #pragma unroll
            for (int nt = 0; nt < 4; nt++) {
                #pragma unroll
                for (int i = 0; i < 2; i++) {
                    int cg = col0 + warpN + nt * 8 + 2 * t4 + i;
                    float v = acc[mt][nt][half * 2 + i];
                    if (cg < NQ) s += __expf(v * trow - M0);
                }
            }
            s += __shfl_xor_sync(0xffffffffu, s, 1);
            s += __shfl_xor_sync(0xffffffffu, s, 2);
            if (t4 == 0) atomicAdd(&g_Zq[rg], s);
        }
    }
}

// ---------------- stage F: final loss ----------------
__global__ void k_final(float* __restrict__ out) {
    __shared__ float red[1024];
    float s = 0.0f;
    for (int r = threadIdx.x; r < NPIX; r += 1024) {
        float Z = g_Zs[r] + g_Zq[r];
        s += M0 + logf(Z) - g_l0[r];
    }
    red[threadIdx.x] = s;
    __syncthreads();
    for (int o = 512; o; o >>= 1) {
        if (threadIdx.x < o) red[threadIdx.x] += red[threadIdx.x + o];
        __syncthreads();
    }
    if (threadIdx.x == 0) out[0] = red[0] * (1.0f / (float)NPIX);
}

// ---------------- launch ----------------
extern "C" void kernel_launch(void* const* d_in, const int* in_sizes, int n_in,
                              void* d_out, int out_size) {
    const float* ref = (const float*)d_in[0];
    const float* tgt = (const float*)d_in[1];
    const float* tl  = (const float*)d_in[2];
    const float* tr  = (const float*)d_in[3];
    const float* que = (const float*)d_in[4];

    k_mask  <<<Bz, 1024>>>(tl, tr);
    k_trans <<<2048, 256>>>(ref, 1);
    k_trans <<<2048, 256>>>(tgt, 0);
    k_queue <<<(NQP + 255) / 256, 256>>>(que);
    k_posneg<<<2048, 256>>>();
    dim3 gg(NQP / 128, NPIX / 128);
    k_gemm_bf16<<<gg, 256>>>();
    k_final <<<1, 1024>>>((float*)d_out);
}

// round 13
// speedup vs baseline: 2.2902x; 1.0284x over previous
#include <cuda_runtime.h>
#include <cuda_bf16.h>
#include <math.h>

typedef unsigned int u32;

#define Bz   2
#define Cz   128
#define Hz   64
#define Wz   128
#define HW   8192
#define NPIX 16384
#define NQ   6000
#define NQP  6016
#define NNEG 60
#define M0   14.2857151031494140625f   /* float(1/0.07) */
#define INVT 14.2857151031494140625f

// ---------------- scratch (device globals; no allocation) ----------------
__device__ __align__(16) float g_Q [NPIX * Cz];            // normalized query fp32, [row][c]
__device__ __align__(16) float g_T [NPIX * Cz];            // tgt transposed,   [row][c]
__device__ __align__(16) __nv_bfloat16 g_Qb [NPIX * Cz];   // bf16 query for GEMM, [row][c]
__device__ __align__(16) __nv_bfloat16 g_QNb[Cz * NQP];    // bf16 queue, [c][k] (pad cols zero)
__device__ float g_t [NPIX];   // per-row logits scale (mask ? 1/T : 0)
__device__ float g_dl[NPIX];   // per-row disparity
__device__ float g_Zs[NPIX];   // exp-sum of pos + 60 negs (shifted by M0)
__device__ float g_l0[NPIX];   // logit of class 0
__device__ float g_Zq[NPIX];   // exp-sum over queue logits (atomic)

// ---------------- threefry2x32 (JAX) ----------------
__device__ __forceinline__ void tfry(u32 k0, u32 k1, u32 x0, u32 x1, u32& o0, u32& o1) {
    u32 k2 = k0 ^ k1 ^ 0x1BD11BDAu;
    x0 += k0; x1 += k1;
#define RND4(a,b,c,d) \
    x0 += x1; x1 = __funnelshift_l(x1, x1, a); x1 ^= x0; \
    x0 += x1; x1 = __funnelshift_l(x1, x1, b); x1 ^= x0; \
    x0 += x1; x1 = __funnelshift_l(x1, x1, c); x1 ^= x0; \
    x0 += x1; x1 = __funnelshift_l(x1, x1, d); x1 ^= x0;
    RND4(13,15,26,6)   x0 += k1; x1 += k2 + 1u;
    RND4(17,29,16,24)  x0 += k2; x1 += k0 + 2u;
    RND4(13,15,26,6)   x0 += k0; x1 += k1 + 3u;
    RND4(17,29,16,24)  x0 += k1; x1 += k2 + 4u;
    RND4(13,15,26,6)   x0 += k2; x1 += k0 + 5u;
#undef RND4
    o0 = x0; o1 = x1;
}
__device__ __forceinline__ u32 rbits(u32 k0, u32 k1, u32 ctr) {
    u32 a, b; tfry(k0, k1, 0u, ctr, a, b); return a ^ b;
}

// ---------------- grid_sample axis helper ----------------
__device__ __forceinline__ void gs_axis(float g, int size, int& i0, int& i1, float& wf) {
    float gx = 2.0f * g - 1.0f;
    float ix = (gx + 1.0f) * ((float)size * 0.5f) - 0.5f;
    ix = fminf(fmaxf(ix, 0.0f), (float)(size - 1));
    float f0 = floorf(ix);
    i0 = (int)f0;
    i1 = min(i0 + 1, size - 1);
    wf = ix - f0;
}

// ---------------- cp.async helpers ----------------
__device__ __forceinline__ void cpa16(u32 dst, const void* src) {
    asm volatile("cp.async.cg.shared.global [%0], [%1], 16;" :: "r"(dst), "l"(src));
}

// ================= fused prep kernel =================
// blocks [0,2): mask/disparity  [2,2050): trans ref  [2050,4098): trans tgt  [4098,4122): queue
__global__ __launch_bounds__(256) void k_prep(const float* __restrict__ ref,
                                              const float* __restrict__ tgt,
                                              const float* __restrict__ tl,
                                              const float* __restrict__ tr,
                                              const float* __restrict__ q) {
    int bid = blockIdx.x;
    if (bid < 2) {
        // ---- mask ----
        int b = bid;
        __shared__ float A[HW];
        const float* TL = tl + b * (256 * 512);
        const float* TR = tr + b * (256 * 512);
        for (int p = threadIdx.x; p < HW; p += 256) {
            int h = p >> 7, w = p & 127;
            float dr = TR[(4 * h) * 512 + 4 * w] * 0.25f;
            float xb = (float)w * (1.0f / 127.0f);
            int x0, x1; float wx;
            gs_axis(xb + dr * (1.0f / 128.0f), Wz, x0, x1, wx);
            A[p] = (float)x0 * (1.0f - wx) + (float)x1 * wx;
        }
        __syncthreads();
        for (int p = threadIdx.x; p < HW; p += 256) {
            int h = p >> 7, w = p & 127;
            float dl = TL[(4 * h) * 512 + 4 * w] * 0.25f;
            float xb = (float)w * (1.0f / 127.0f);
            float yb = (float)h * (1.0f / 63.0f);
            int x0, x1, y0, y1; float wx, wy;
            gs_axis(xb - dl * (1.0f / 128.0f), Wz, x0, x1, wx);
            gs_axis(yb, Hz, y0, y1, wy);
            float v = A[y0 * Wz + x0] * (1.0f - wx) * (1.0f - wy)
                    + A[y0 * Wz + x1] * wx * (1.0f - wy)
                    + A[y1 * Wz + x0] * (1.0f - wx) * wy
                    + A[y1 * Wz + x1] * wx * wy;
            bool m = (fabsf((float)w - v) < 3.0f) && (dl > 0.0f)
                     && (xb - dl * (1.0f / 128.0f) >= 0.0f);
            int row = b * HW + p;
            g_t [row] = m ? INVT : 0.0f;
            g_dl[row] = dl;
            g_Zq[row] = 0.0f;
        }
    } else if (bid < 4098) {
        // ---- transpose (+ normalize + bf16 for ref) ----
        int do_norm = (bid < 2050) ? 1 : 0;
        int base = do_norm ? 2 : 2050;
        int gw   = ((bid - base) * 256 + threadIdx.x) >> 5;
        int lane = threadIdx.x & 31;
        const float* src = do_norm ? ref : tgt;
        int b = gw >> 13, p = gw & (HW - 1);
        const float* S = src + b * Cz * HW + p;
        float v0 = S[(lane      ) * HW];
        float v1 = S[(lane + 32 ) * HW];
        float v2 = S[(lane + 64 ) * HW];
        float v3 = S[(lane + 96 ) * HW];
        float s = 1.0f;
        if (do_norm) {
            float ss = v0 * v0 + v1 * v1 + v2 * v2 + v3 * v3;
            #pragma unroll
            for (int o = 16; o; o >>= 1) ss += __shfl_xor_sync(0xffffffffu, ss, o);
            s = 1.0f / fmaxf(sqrtf(ss), 1e-12f);
        }
        v0 *= s; v1 *= s; v2 *= s; v3 *= s;
        float* D = (do_norm ? g_Q : g_T) + gw * Cz;
        D[lane] = v0; D[lane + 32] = v1; D[lane + 64] = v2; D[lane + 96] = v3;
        if (do_norm) {
            __nv_bfloat16* Db = g_Qb + gw * Cz;
            Db[lane]      = __float2bfloat16_rn(v0);
            Db[lane + 32] = __float2bfloat16_rn(v1);
            Db[lane + 64] = __float2bfloat16_rn(v2);
            Db[lane + 96] = __float2bfloat16_rn(v3);
        }
    } else {
        // ---- queue normalize ----
        int k = (bid - 4098) * 256 + threadIdx.x;
        if (k >= NQP) return;
        if (k >= NQ) {
            for (int c = 0; c < Cz; c++) g_QNb[c * NQP + k] = __float2bfloat16_rn(0.0f);
            return;
        }
        float ss = 0.0f;
        for (int c = 0; c < Cz; c++) { float v = q[c * NQ + k]; ss += v * v; }
        float inv = 1.0f / fmaxf(sqrtf(ss), 1e-12f);
        for (int c = 0; c < Cz; c++)
            g_QNb[c * NQP + k] = __float2bfloat16_rn(q[c * NQ + k] * inv);
    }
}

// ---------------- positive + 60 negatives per pixel ----------------
__global__ void k_posneg() {
    __shared__ __align__(16) float sq [8][Cz];
    __shared__ float sfx[8][NNEG];
    int wip = threadIdx.x >> 5, lane = threadIdx.x & 31;
    int row = blockIdx.x * 8 + wip;
    int b = row >> 13, p = row & (HW - 1);
    int h = p >> 7, w = p & 127;

    const float* Qr = g_Q + row * Cz;
    sq[wip][lane]      = Qr[lane];
    sq[wip][lane + 32] = Qr[lane + 32];
    sq[wip][lane + 64] = Qr[lane + 64];
    sq[wip][lane + 96] = Qr[lane + 96];

    float t  = g_t[row];
    float dl = g_dl[row];
    float xb = (float)w * (1.0f / 127.0f);
    float yb = (float)h * (1.0f / 63.0f);
    float gx = xb - dl * (1.0f / 128.0f);
    float xr = gx * 128.0f;

    u32 ka0, ka1, kb0, kb1;
    tfry(0u, 1234u, 0u, 0u, ka0, ka1);
    tfry(0u, 1234u, 0u, 1u, kb0, kb1);
    for (int n = lane; n < NNEG; n += 32) {
        u32 i  = (u32)(row * NNEG + n);
        u32 hi = rbits(ka0, ka1, i);
        u32 lo = rbits(ka0, ka1, (u32)(NPIX * NNEG) + i);
        float mag = 1.0f + (float)(((hi % 24u) * 16u + (lo % 24u)) % 24u);
        u32 ub = rbits(kb0, kb1, i);
        float u  = __uint_as_float((ub >> 9) | 0x3f800000u) - 1.0f;
        float sg = (u > 0.5f) ? 1.0f : ((u < 0.5f) ? -1.0f : 0.0f);
        float fv = xr + mag * sg;
        float m  = fmodf(fv, 128.0f); if (m < 0.0f) m += 128.0f;
        sfx[wip][n] = m * (1.0f / 128.0f);
    }
    __syncwarp();

    const float* T = g_T + b * HW * Cz;
    float4 q4 = ((const float4*)sq[wip])[lane];

    // positive
    int x0, x1, y0, y1; float wx, wy;
    gs_axis(gx, Wz, x0, x1, wx);
    gs_axis(yb, Hz, y0, y1, wy);
    float w00 = (1.0f - wx) * (1.0f - wy), w01 = wx * (1.0f - wy);
    float w10 = (1.0f - wx) * wy,          w11 = wx * wy;
    float4 A0 = ((const float4*)(T + (y0 * Wz + x0) * Cz))[lane];
    float4 A1 = ((const float4*)(T + (y0 * Wz + x1) * Cz))[lane];
    float4 A2 = ((const float4*)(T + (y1 * Wz + x0) * Cz))[lane];
    float4 A3 = ((const float4*)(T + (y1 * Wz + x1) * Cz))[lane];
    float vx = w00 * A0.x + w01 * A1.x + w10 * A2.x + w11 * A3.x;
    float vy = w00 * A0.y + w01 * A1.y + w10 * A2.y + w11 * A3.y;
    float vz = w00 * A0.z + w01 * A1.z + w10 * A2.z + w11 * A3.z;
    float vw = w00 * A0.w + w01 * A1.w + w10 * A2.w + w11 * A3.w;
    float qv = q4.x * vx + q4.y * vy + q4.z * vz + q4.w * vw;
    float vv = vx * vx + vy * vy + vz * vz + vw * vw;
    #pragma unroll
    for (int o = 16; o; o >>= 1) {
        qv += __shfl_xor_sync(0xffffffffu, qv, o);
        vv += __shfl_xor_sync(0xffffffffu, vv, o);
    }
    float lpos = qv / fmaxf(sqrtf(vv), 1e-12f);
    float l0   = lpos * t;
    float Zall = __expf(l0 - M0);

    // negatives: 2 at a time, interleaved reduction chains; skip row-1 taps when wy==0
    #pragma unroll 1
    for (int n = 0; n < NNEG; n += 2) {
        float nqv[2], nvv[2];
        #pragma unroll
        for (int s = 0; s < 2; s++) {
            float fx = sfx[wip][n + s];
            float fy = fx * (1.0f / 64.0f);
            int nx0, nx1, ny0, ny1; float nwx, nwy;
            gs_axis(fx, Wz, nx0, nx1, nwx);
            gs_axis(fy, Hz, ny0, ny1, nwy);
            float c00 = (1.0f - nwx) * (1.0f - nwy), c01 = nwx * (1.0f - nwy);
            float4 B0 = ((const float4*)(T + (ny0 * Wz + nx0) * Cz))[lane];
            float4 B1 = ((const float4*)(T + (ny0 * Wz + nx1) * Cz))[lane];
            float ux = c00 * B0.x + c01 * B1.x;
            float uy = c00 * B0.y + c01 * B1.y;
            float uz = c00 * B0.z + c01 * B1.z;
            float uw = c00 * B0.w + c01 * B1.w;
            if (nwy > 0.0f) {
                float c10 = (1.0f - nwx) * nwy, c11 = nwx * nwy;
                float4 B2 = ((const float4*)(T + (ny1 * Wz + nx0) * Cz))[lane];
                float4 B3 = ((const float4*)(T + (ny1 * Wz + nx1) * Cz))[lane];
                ux += c10 * B2.x + c11 * B3.x;
                uy += c10 * B2.y + c11 * B3.y;
                uz += c10 * B2.z + c11 * B3.z;
                uw += c10 * B2.w + c11 * B3.w;
            }
            nqv[s] = q4.x * ux + q4.y * uy + q4.z * uz + q4.w * uw;
            nvv[s] = ux * ux + uy * uy + uz * uz + uw * uw;
        }
        #pragma unroll
        for (int o = 16; o; o >>= 1) {
            nqv[0] += __shfl_xor_sync(0xffffffffu, nqv[0], o);
            nvv[0] += __shfl_xor_sync(0xffffffffu, nvv[0], o);
            nqv[1] += __shfl_xor_sync(0xffffffffu, nqv[1], o);
            nvv[1] += __shfl_xor_sync(0xffffffffu, nvv[1], o);
        }
        Zall += __expf(nqv[0] / fmaxf(sqrtf(nvv[0]), 1e-12f) * t - M0);
        Zall += __expf(nqv[1] / fmaxf(sqrtf(nvv[1]), 1e-12f) * t - M0);
    }
    if (lane == 0) { g_Zs[row] = Zall; g_l0[row] = l0; }
}

// ---------------- bf16 tensor-core GEMM, cp.async double-buffered ----------------
#define LDAe 72    /* A smem stride (bf16): 64 k + 8 pad */
#define LDBe 136   /* B smem stride (bf16): 128 n + 8 pad */
#define ASZ  (128 * LDAe)
#define BSZ  (64 * LDBe)
#define BUFSZ (ASZ + BSZ)
__global__ __launch_bounds__(256, 2) void k_gemm_bf16() {
    extern __shared__ __align__(16) __nv_bfloat16 sm[];
    int tid  = threadIdx.x;
    int lane = tid & 31, wid = tid >> 5;
    int gid  = lane >> 2, t4 = lane & 3;
    int warpM = (wid & 1) * 64;
    int warpN = (wid >> 1) * 32;
    int row0 = blockIdx.y * 128;
    int col0 = blockIdx.x * 128;

    const __nv_bfloat16* Ag = g_Qb  + row0 * Cz;
    const __nv_bfloat16* Bg = g_QNb + col0;

    u32 smB = (u32)__cvta_generic_to_shared(sm);

    // issue both K-chunks with cp.async
    #pragma unroll
    for (int buf = 0; buf < 2; buf++) {
        int kc = buf * 64;
        u32 aB = smB + buf * BUFSZ * 2;
        u32 bB = aB + ASZ * 2;
        #pragma unroll
        for (int pass = 0; pass < 4; pass++) {
            int m  = pass * 32 + (tid >> 3);
            int k8 = (tid & 7) * 8;
            cpa16(aB + (m * LDAe + k8) * 2, Ag + m * Cz + kc + k8);
        }
        #pragma unroll
        for (int pass = 0; pass < 4; pass++) {
            int k = pass * 16 + (tid >> 4);
            int n = (tid & 15) * 8;
            cpa16(bB + (k * LDBe + n) * 2, Bg + (kc + k) * NQP + n);
        }
        asm volatile("cp.async.commit_group;");
    }

    int aR = (lane & 7) + ((lane >> 3) & 1) * 8;
    int aK = (lane >> 4) * 8;
    int bK = (lane & 7) + ((lane >> 3) & 1) * 8;
    int bN = (lane >> 4) * 8;

    float acc[4][4][4];
    #pragma unroll
    for (int a = 0; a < 4; a++)
        #pragma unroll
        for (int b = 0; b < 4; b++)
            #pragma unroll
            for (int c = 0; c < 4; c++) acc[a][b][c] = 0.0f;

    #pragma unroll
    for (int buf = 0; buf < 2; buf++) {
        if (buf == 0) asm volatile("cp.async.wait_group 1;");
        else          asm volatile("cp.async.wait_group 0;");
        __syncthreads();
        u32 asB = smB + buf * BUFSZ * 2;
        u32 bsB = asB + ASZ * 2;
        #pragma unroll
        for (int kk = 0; kk < 64; kk += 16) {
            u32 afr[4][4]; u32 bfr[4][2];
            #pragma unroll
            for (int mt = 0; mt < 4; mt++) {
                u32 addr = asB + ((warpM + mt * 16 + aR) * LDAe + kk + aK) * 2;
                asm volatile("ldmatrix.sync.aligned.m8n8.x4.shared.b16 {%0,%1,%2,%3}, [%4];"
                             : "=r"(afr[mt][0]), "=r"(afr[mt][1]),
                               "=r"(afr[mt][2]), "=r"(afr[mt][3]) : "r"(addr));
            }
            #pragma unroll
            for (int np = 0; np < 2; np++) {
                u32 addr = bsB + ((kk + bK) * LDBe + warpN + np * 16 + bN) * 2;
                asm volatile("ldmatrix.sync.aligned.m8n8.x4.trans.shared.b16 {%0,%1,%2,%3}, [%4];"
                             : "=r"(bfr[np * 2][0]),     "=r"(bfr[np * 2][1]),
                               "=r"(bfr[np * 2 + 1][0]), "=r"(bfr[np * 2 + 1][1]) : "r"(addr));
            }
            #pragma unroll
            for (int mt = 0; mt < 4; mt++)
                #pragma unroll
                for (int nt = 0; nt < 4; nt++) {
                    float* d = acc[mt][nt];
                    asm volatile(
                        "mma.sync.aligned.m16n8k16.row.col.f32.bf16.bf16.f32 "
                        "{%0,%1,%2,%3}, {%4,%5,%6,%7}, {%8,%9}, {%0,%1,%2,%3};"
                        : "+f"(d[0]), "+f"(d[1]), "+f"(d[2]), "+f"(d[3])
                        : "r"(afr[mt][0]), "r"(afr[mt][1]), "r"(afr[mt][2]), "r"(afr[mt][3]),
                          "r"(bfr[nt][0]), "r"(bfr[nt][1]));
                }
        }
    }

    // epilogue: exp + row partial sums (skip padded cols >= NQ)
    #pragma unroll
    for (int mt = 0; mt < 4; mt++) {
        #pragma unroll
        for (int half = 0; half < 2; half++) {
            int rg = row0 + warpM + mt * 16 + gid + half * 8;
            float trow = g_t[rg];
            float s = 0.0f;
            #pragma unroll
            for (int nt = 0; nt < 4; nt++) {
                #pragma unroll
                for (int i = 0; i < 2; i++) {
                    int cg = col0 + warpN + nt * 8 + 2 * t4 + i;
                    float v = acc[mt][nt][half * 2 + i];
                    if (cg < NQ) s += __expf(v * trow - M0);
                }
            }
            s += __shfl_xor_sync(0xffffffffu, s, 1);
            s += __shfl_xor_sync(0xffffffffu, s, 2);
            if (t4 == 0) atomicAdd(&g_Zq[rg], s);
        }
    }
}

// ---------------- final loss ----------------
__global__ void k_final(float* __restrict__ out) {
    __shared__ float red[1024];
    float s = 0.0f;
    for (int r = threadIdx.x; r < NPIX; r += 1024) {
        float Z = g_Zs[r] + g_Zq[r];
        s += M0 + logf(Z) - g_l0[r];
    }
    red[threadIdx.x] = s;
    __syncthreads();
    for (int o = 512; o; o >>= 1) {
        if (threadIdx.x < o) red[threadIdx.x] += red[threadIdx.x + o];
        __syncthreads();
    }
    if (threadIdx.x == 0) out[0] = red[0] * (1.0f / (float)NPIX);
}

// ---------------- launch ----------------
extern "C" void kernel_launch(void* const* d_in, const int* in_sizes, int n_in,
                              void* d_out, int out_size) {
    const float* ref = (const float*)d_in[0];
    const float* tgt = (const float*)d_in[1];
    const float* tl  = (const float*)d_in[2];
    const float* tr  = (const float*)d_in[3];
    const float* que = (const float*)d_in[4];

    static int smem_set = 0;
    if (!smem_set) {
        cudaFuncSetAttribute(k_gemm_bf16,
                             cudaFuncAttributeMaxDynamicSharedMemorySize,
                             2 * BUFSZ * 2);
        smem_set = 1;
    }

    k_prep  <<<4122, 256>>>(ref, tgt, tl, tr, que);
    k_posneg<<<2048, 256>>>();
    dim3 gg(NQP / 128, NPIX / 128);
    k_gemm_bf16<<<gg, 256, 2 * BUFSZ * 2>>>();
    k_final <<<1, 1024>>>((float*)d_out);
}